// round 5
// baseline (speedup 1.0000x reference)
#include <cuda_runtime.h>
#include <cuda_bf16.h>
#include <cstdint>

// GCN sparse aggregation: out[r,:] += vals[e] * embeds[cols[e],:]
// N=100000 nodes, E=1600000 edges, D=64, fp32.
//
// Round 4: counting-sort CSR with a minimized pipeline (5 launches):
//   1) hist : count[rows[e]]++            (g_count starts zeroed; scan1 re-zeroes)
//   2) scan1: block-exclusive prefix of counts -> g_cursor, block totals;
//             zeroes g_count for the next execution (deterministic invariant)
//   3) scan3: every block scans the 196 block-sums in smem (redundant, cheap)
//             -> g_rowstart, g_cursor   (scan2 kernel fused away)
//   4) place: slot = cursor[r]++; g_edge[slot] = {col, val}
//   5) aggregate: one WARP per node, each lane owns a float2 of the D=64 row;
//      contiguous CSR range, unroll-4 independent loads, reg accumulation,
//      single coalesced float2 store. Output fully overwritten -> no zero pass.

#define D_FEAT 64
#define NV 100000
#define NE 1600000
#define SCAN_BS 512
#define NB ((NV + SCAN_BS - 1) / SCAN_BS)   // 196

__device__ int  g_count[NV];        // zero-initialized at load; kept zero between runs
__device__ int  g_cursor[NV];
__device__ int  g_rowstart[NV + 1];
__device__ int  g_blocksum[NB];
__device__ int2 g_edge[NE];         // {col, val_bits}, grouped by row

__global__ void __launch_bounds__(256) hist_kernel(
    const int* __restrict__ rows, int n_edges)
{
    int e = blockIdx.x * blockDim.x + threadIdx.x;
    if (e < n_edges) atomicAdd(&g_count[rows[e]], 1);
}

// Block-exclusive scan; also resets g_count to 0 for the next execution.
__global__ void __launch_bounds__(SCAN_BS) scan1_kernel(int n_nodes) {
    __shared__ int sm[SCAN_BS];
    int g = blockIdx.x * SCAN_BS + threadIdx.x;
    int v = 0;
    if (g < n_nodes) {
        v = g_count[g];
        g_count[g] = 0;                 // restore invariant for next run
    }
    sm[threadIdx.x] = v;
    __syncthreads();
    for (int off = 1; off < SCAN_BS; off <<= 1) {
        int t = (threadIdx.x >= off) ? sm[threadIdx.x - off] : 0;
        __syncthreads();
        sm[threadIdx.x] += t;
        __syncthreads();
    }
    if (g < n_nodes) g_cursor[g] = sm[threadIdx.x] - v;   // exclusive within block
    if (threadIdx.x == SCAN_BS - 1) g_blocksum[blockIdx.x] = sm[SCAN_BS - 1];
}

// Fused block-offset scan + finalize: every block redundantly scans the 196
// block sums (784B, L2-hot broadcast) and applies its own offset.
__global__ void __launch_bounds__(SCAN_BS) scan3_kernel(int n_nodes, int n_edges) {
    __shared__ int bs[256];
    int tid = threadIdx.x;
    if (tid < 256) bs[tid] = (tid < NB) ? g_blocksum[tid] : 0;
    __syncthreads();
    for (int off = 1; off < 256; off <<= 1) {
        int t = (tid >= off && tid < 256) ? bs[tid - off] : 0;
        __syncthreads();
        if (tid < 256) bs[tid] += t;
        __syncthreads();
    }
    int blockoff = (blockIdx.x == 0) ? 0 : bs[blockIdx.x - 1];
    int g = blockIdx.x * SCAN_BS + tid;
    if (g < n_nodes) {
        int rs = g_cursor[g] + blockoff;
        g_rowstart[g] = rs;
        g_cursor[g]   = rs;
    }
    if (g == 0) g_rowstart[n_nodes] = n_edges;
}

__global__ void __launch_bounds__(256) place_kernel(
    const int*   __restrict__ rows,
    const int*   __restrict__ cols,
    const float* __restrict__ vals,
    int n_edges)
{
    int e = blockIdx.x * blockDim.x + threadIdx.x;
    if (e >= n_edges) return;
    int r = rows[e];
    int pos = atomicAdd(&g_cursor[r], 1);
    g_edge[pos] = make_int2(cols[e], __float_as_int(vals[e]));
}

__global__ void __launch_bounds__(256) aggregate_kernel(
    const float2* __restrict__ embeds2,   // [NV, 32] float2
    float2*       __restrict__ out2,      // [NV, 32] float2
    int n_nodes)
{
    int w    = (blockIdx.x * blockDim.x + threadIdx.x) >> 5;  // node = warp
    int lane = threadIdx.x & 31;
    if (w >= n_nodes) return;

    int i   = g_rowstart[w];
    int end = g_rowstart[w + 1];

    float ax = 0.f, ay = 0.f;

    for (; i + 3 < end; i += 4) {
        int2 p0 = __ldg(&g_edge[i]);
        int2 p1 = __ldg(&g_edge[i + 1]);
        int2 p2 = __ldg(&g_edge[i + 2]);
        int2 p3 = __ldg(&g_edge[i + 3]);
        float2 x0 = __ldg(&embeds2[(size_t)p0.x * 32 + lane]);
        float2 x1 = __ldg(&embeds2[(size_t)p1.x * 32 + lane]);
        float2 x2 = __ldg(&embeds2[(size_t)p2.x * 32 + lane]);
        float2 x3 = __ldg(&embeds2[(size_t)p3.x * 32 + lane]);
        float v0 = __int_as_float(p0.y);
        float v1 = __int_as_float(p1.y);
        float v2 = __int_as_float(p2.y);
        float v3 = __int_as_float(p3.y);
        ax += v0 * x0.x; ay += v0 * x0.y;
        ax += v1 * x1.x; ay += v1 * x1.y;
        ax += v2 * x2.x; ay += v2 * x2.y;
        ax += v3 * x3.x; ay += v3 * x3.y;
    }
    for (; i < end; ++i) {
        int2 p = __ldg(&g_edge[i]);
        float v = __int_as_float(p.y);
        float2 x = __ldg(&embeds2[(size_t)p.x * 32 + lane]);
        ax += v * x.x; ay += v * x.y;
    }
    out2[(size_t)w * 32 + lane] = make_float2(ax, ay);
}

extern "C" void kernel_launch(void* const* d_in, const int* in_sizes, int n_in,
                              void* d_out, int out_size)
{
    const int*   rows   = (const int*)d_in[0];
    const int*   cols   = (const int*)d_in[1];
    const float* vals   = (const float*)d_in[2];
    const float* embeds = (const float*)d_in[3];
    int n_edges = in_sizes[0];
    if (n_edges > NE) n_edges = NE;
    int n_nodes = out_size / D_FEAT;
    if (n_nodes > NV) n_nodes = NV;

    float* out = (float*)d_out;

    {   // 1) histogram (g_count is zero on entry, by init or by scan1 reset)
        int threads = 256;
        int blocks = (n_edges + threads - 1) / threads;
        hist_kernel<<<blocks, threads>>>(rows, n_edges);
    }
    {   // 2-3) exclusive scan (2 launches, scan2 fused into scan3)
        scan1_kernel<<<NB, SCAN_BS>>>(n_nodes);
        scan3_kernel<<<NB, SCAN_BS>>>(n_nodes, n_edges);
    }
    {   // 4) place edges into CSR slots
        int threads = 256;
        int blocks = (n_edges + threads - 1) / threads;
        place_kernel<<<blocks, threads>>>(rows, cols, vals, n_edges);
    }
    {   // 5) aggregate: warp per node (out fully overwritten, no zero pass)
        long long total = (long long)n_nodes * 32;
        int threads = 256;
        int blocks = (int)((total + threads - 1) / threads);
        aggregate_kernel<<<blocks, threads>>>(
            (const float2*)embeds, (float2*)out, n_nodes);
    }
}